// round 12
// baseline (speedup 1.0000x reference)
#include <cuda_runtime.h>
#include <cstdint>

#define DIMS   120
#define NPIX   14400        // 120*120
#define SS2    81
#define B64    64
#define PITCH  92           // banks 28g+q all-distinct for scalar fragment loads
#define V4PIX  841          // 29*29
#define FLATN  13456        // 16*841
#define PPB    10           // pixels per v1 block (same image row)

// Intermediates (allocation-free scratch)
__device__ float g_cplx[8 * NPIX * B64];    // [s][pix][b]
__device__ float g_part[V4PIX * 128];       // [p][b*2+cls] decision partials

__device__ __forceinline__ void cp_async4(void* smem_dst, const void* gmem_src) {
    unsigned s = (unsigned)__cvta_generic_to_shared(smem_dst);
    asm volatile("cp.async.ca.shared.global [%0], [%1], 4;" :: "r"(s), "l"(gmem_src));
}
__device__ __forceinline__ void cp_async16(void* smem_dst, const void* gmem_src) {
    unsigned s = (unsigned)__cvta_generic_to_shared(smem_dst);
    asm volatile("cp.async.cg.shared.global [%0], [%1], 16;" :: "r"(s), "l"(gmem_src));
}
__device__ __forceinline__ void cp_commit() {
    asm volatile("cp.async.commit_group;");
}
__device__ __forceinline__ uint32_t to_tf32(float f) {
    uint32_t r;
    asm("cvt.rna.tf32.f32 %0, %1;" : "=r"(r) : "f"(f));
    return r;
}

// ---------------------------------------------------------------------------
// V1 via mma.sync m16n8k8 tf32 (R10 GEMM path — scalar LDS.32 fragment loads,
// bank-perfect at pitch 92) with 4-warp-balanced patch staging.
// ---------------------------------------------------------------------------
__global__ __launch_bounds__(128)
void v1_kernel(const float* __restrict__ x, const float* __restrict__ w)
{
    extern __shared__ __align__(16) float sm[];
    float (*w_s)[32][PITCH] = (float (*)[32][PITCH])sm;                // [2][32][92]
    float (*p_s)[PITCH]     = (float (*)[PITCH])(sm + 2 * 32 * PITCH); // [64][92]
    float* bounce           = sm + 2 * 32 * PITCH + 64 * PITCH;       // [8*64]

    int t = threadIdx.x;
    int lane = t & 31, wid = t >> 5;
    int g = lane >> 2;
    int q = lane & 3;

    int row_i = blockIdx.x / 12;
    int j0    = (blockIdx.x % 12) * 10;
    int p0    = row_i * DIMS + j0;

    // zero k-padding cols 81..91 for all 128 rows, once
    {
        float* rowp = (t < 64) ? &w_s[t >> 5][t & 31][0] : &p_s[t - 64][0];
#pragma unroll
        for (int c = 81; c < 92; c++) rowp[c] = 0.f;
    }

    // per-lane staging constants for the 3 k-chunks: k = lane, +32, +64
    int rr[3], qq[3];
#pragma unroll
    for (int c = 0; c < 3; c++) {
        int k = lane + 32 * c;
        rr[c] = k / 9;
        qq[c] = k - 9 * rr[c];
    }

    // weight staging: pixel p -> w_s[buf][c][k], warp-per-channel, coalesced
    auto wpre = [&](int p, int buf) {
#pragma unroll
        for (int gg = 0; gg < 8; gg++) {
            int c = wid * 8 + gg;
            const float* src = w + (c * NPIX + p) * SS2 + lane;
            float* dst = &w_s[buf][c][lane];
            cp_async4(dst, src);
            cp_async4(dst + 32, src + 32);
            if (lane < 17) cp_async4(dst + 64, src + 64);
        }
    };
    // patch staging, balanced: warp w owns batches [16w, 16w+16);
    // lane owns k-chunks lane, lane+32, lane+64 (constant strides).
    auto ppre = [&](int j) {
        const float* xw = x + (row_i << 7) + j + (wid << 18);   // +16*wid batches
        float* pw = &p_s[wid << 4][0];
#pragma unroll
        for (int c = 0; c < 3; c++) {
            if (c < 2 || lane < 17) {
                const float* src = xw + (rr[c] << 7) + qq[c];
                float* dst = pw + lane + 32 * c;
#pragma unroll
                for (int b = 0; b < 16; b++)
                    cp_async4(dst + b * PITCH, src + (b << 14));
            }
        }
    };

    wpre(p0, 0);
    cp_commit();
    ppre(j0);
    cp_commit();

    for (int n = 0; n < PPB; n++) {
        int p   = p0 + n;
        int buf = n & 1;

        if (n + 1 < PPB) {
            wpre(p + 1, buf ^ 1);
            cp_commit();
            asm volatile("cp.async.wait_group 1;");
        } else {
            asm volatile("cp.async.wait_group 0;");
        }
        __syncthreads();

        float d[4][4];
#pragma unroll
        for (int nt = 0; nt < 4; nt++)
#pragma unroll
            for (int r = 0; r < 4; r++) d[nt][r] = 0.f;

        const float (*wb)[PITCH] = w_s[buf];
        const float (*pb)[PITCH] = p_s;

#pragma unroll
        for (int kt = 0; kt < 11; kt++) {
            int k0 = kt * 8;
            uint32_t a0 = to_tf32(pb[16 * wid + g][k0 + q]);
            uint32_t a1 = to_tf32(pb[16 * wid + g + 8][k0 + q]);
            uint32_t a2 = to_tf32(pb[16 * wid + g][k0 + q + 4]);
            uint32_t a3 = to_tf32(pb[16 * wid + g + 8][k0 + q + 4]);
#pragma unroll
            for (int nt = 0; nt < 4; nt++) {
                uint32_t b0 = to_tf32(wb[8 * nt + g][k0 + q]);
                uint32_t b1 = to_tf32(wb[8 * nt + g][k0 + q + 4]);
                asm volatile(
                    "mma.sync.aligned.m16n8k8.row.col.f32.tf32.tf32.f32 "
                    "{%0,%1,%2,%3}, {%4,%5,%6,%7}, {%8,%9}, {%0,%1,%2,%3};"
                    : "+f"(d[nt][0]), "+f"(d[nt][1]), "+f"(d[nt][2]), "+f"(d[nt][3])
                    : "r"(a0), "r"(a1), "r"(a2), "r"(a3), "r"(b0), "r"(b1));
            }
        }
        __syncthreads();

        if (n + 1 < PPB) {
            ppre(j0 + n + 1);
            cp_commit();
        }

        // relu + phase-mean
#pragma unroll
        for (int nt = 0; nt < 4; nt++) {
            float r01 = fmaxf(d[nt][0], 0.f) + fmaxf(d[nt][1], 0.f);
            float r23 = fmaxf(d[nt][2], 0.f) + fmaxf(d[nt][3], 0.f);
            r01 += __shfl_xor_sync(0xFFFFFFFFu, r01, 1);
            r23 += __shfl_xor_sync(0xFFFFFFFFu, r23, 1);
            if ((lane & 1) == 0) {
                int s = 2 * nt + (q >> 1);
                int b = 16 * wid + g;
                bounce[s * 64 + b]     = r01 * 0.25f;
                bounce[s * 64 + b + 8] = r23 * 0.25f;
            }
        }
        __syncthreads();

        {
            int s2i = t >> 4;
            int m   = t & 15;
            float4 v = *(const float4*)&bounce[s2i * 64 + m * 4];
            *(float4*)&g_cplx[(s2i * NPIX + p) * B64 + m * 4] = v;
        }
        __syncthreads();
    }
}

#define V1_SMEM ((2 * 32 * PITCH + 64 * PITCH + 8 * 64) * 4)

// ---------------------------------------------------------------------------
// V4 via mma.sync m16n8k8 tf32 + fused decision fold (R11, known-good).
// ---------------------------------------------------------------------------
__global__ __launch_bounds__(128)
void v4_kernel(const float* __restrict__ vw, const float* __restrict__ dw)
{
    extern __shared__ __align__(16) float vsm[];
    float* wt   = vsm;            // [2][16][68]
    float* ps   = vsm + 2176;     // [2][64][72]
    float* dwv  = vsm + 11392;    // [2][16]
    float* part = vsm + 11424;    // [128]

    int p  = blockIdx.x;
    int ii = p / 29;
    int jj = p - ii * 29;
    int base_pix = (ii * 4) * DIMS + jj * 4;

    int t = threadIdx.x;
    int lane = t & 31, wid = t >> 5;
    int g = lane >> 2;
    int q = lane & 3;

    if (t < 32)
        dwv[t] = dw[(t >> 4) * FLATN + (t & 15) * V4PIX + p];

    auto stage_w = [&](int s, int buf) {
        if (t < 64) {
            int o = t >> 2, c4 = t & 3;
            const float* src = vw + (((o << 3) + s) * V4PIX + p) * 64 + c4 * 16;
            float* dst = &wt[buf * 1088 + o * 68 + c4 * 16];
#pragma unroll
            for (int j = 0; j < 4; j++)
                cp_async16(dst + j * 4, src + j * 4);
        }
    };
    auto stage_p = [&](int s, int buf) {
#pragma unroll
        for (int f0 = 0; f0 < 8; f0++) {
            int f = t + f0 * 128;
            int pos = f >> 4, bq = f & 15;
            int di = pos >> 3, dj = pos & 7;
            const float* src = g_cplx + (size_t)s * (NPIX * B64)
                             + (base_pix + di * DIMS + dj) * B64 + bq * 4;
            cp_async16(&ps[buf * 4608 + pos * 72 + bq * 4], src);
        }
    };

    float d[2][4];
#pragma unroll
    for (int n = 0; n < 2; n++)
#pragma unroll
        for (int r = 0; r < 4; r++) d[n][r] = 0.f;

    stage_w(0, 0);
    stage_p(0, 0);
    cp_commit();

    for (int s = 0; s < 8; s++) {
        int buf = s & 1;
        if (s < 7) {
            stage_w(s + 1, buf ^ 1);
            stage_p(s + 1, buf ^ 1);
            cp_commit();
            asm volatile("cp.async.wait_group 1;");
        } else {
            asm volatile("cp.async.wait_group 0;");
        }
        __syncthreads();

        const float* wb = &wt[buf * 1088];
        const float* pb = &ps[buf * 4608];

#pragma unroll
        for (int kt = 0; kt < 8; kt++) {
            int k0 = kt * 8;
            uint32_t a0 = to_tf32(wb[g * 68 + k0 + q]);
            uint32_t a1 = to_tf32(wb[(g + 8) * 68 + k0 + q]);
            uint32_t a2 = to_tf32(wb[g * 68 + k0 + q + 4]);
            uint32_t a3 = to_tf32(wb[(g + 8) * 68 + k0 + q + 4]);
#pragma unroll
            for (int nl = 0; nl < 2; nl++) {
                int nt = 2 * wid + nl;
                uint32_t b0 = to_tf32(pb[(k0 + q) * 72 + 8 * nt + g]);
                uint32_t b1 = to_tf32(pb[(k0 + q + 4) * 72 + 8 * nt + g]);
                asm volatile(
                    "mma.sync.aligned.m16n8k8.row.col.f32.tf32.tf32.f32 "
                    "{%0,%1,%2,%3}, {%4,%5,%6,%7}, {%8,%9}, {%0,%1,%2,%3};"
                    : "+f"(d[nl][0]), "+f"(d[nl][1]), "+f"(d[nl][2]), "+f"(d[nl][3])
                    : "r"(a0), "r"(a1), "r"(a2), "r"(a3), "r"(b0), "r"(b1));
            }
        }
        __syncthreads();
    }

    float dw0g = dwv[g],      dw0h = dwv[g + 8];
    float dw1g = dwv[16 + g], dw1h = dwv[16 + g + 8];
#pragma unroll
    for (int nl = 0; nl < 2; nl++) {
        int nt = 2 * wid + nl;
        float c00 = d[nl][0] * dw0g + d[nl][2] * dw0h;
        float c01 = d[nl][1] * dw0g + d[nl][3] * dw0h;
        float c10 = d[nl][0] * dw1g + d[nl][2] * dw1h;
        float c11 = d[nl][1] * dw1g + d[nl][3] * dw1h;
#pragma unroll
        for (int m = 4; m < 32; m <<= 1) {
            c00 += __shfl_xor_sync(0xFFFFFFFFu, c00, m);
            c01 += __shfl_xor_sync(0xFFFFFFFFu, c01, m);
            c10 += __shfl_xor_sync(0xFFFFFFFFu, c10, m);
            c11 += __shfl_xor_sync(0xFFFFFFFFu, c11, m);
        }
        if (g == 0) {
            int b = 8 * nt + 2 * q;
            part[b * 2 + 0]       = c00;
            part[(b + 1) * 2 + 0] = c01;
            part[b * 2 + 1]       = c10;
            part[(b + 1) * 2 + 1] = c11;
        }
    }
    __syncthreads();
    g_part[p * 128 + t] = part[t];
}
#define V4_SMEM (11552 * 4)

// ---------------------------------------------------------------------------
// dec2: parallel deterministic reduction (R11, known-good).
// ---------------------------------------------------------------------------
__global__ __launch_bounds__(256)
void dec2_kernel(const float* __restrict__ db, float* __restrict__ out)
{
    int t = blockIdx.x;          // output index b*2+cls
    int j = threadIdx.x;

    float ssum = 0.f;
    for (int p = j; p < V4PIX; p += 256)
        ssum += g_part[p * 128 + t];

    __shared__ float red[256];
    red[j] = ssum;
    __syncthreads();
    for (int off = 128; off > 0; off >>= 1) {
        if (j < off) red[j] += red[j + off];
        __syncthreads();
    }
    if (j == 0) out[t] = red[0] + db[t & 1];
}

// ---------------------------------------------------------------------------
extern "C" void kernel_launch(void* const* d_in, const int* in_sizes, int n_in,
                              void* d_out, int out_size)
{
    const float* x  = (const float*)d_in[0];   // [64,1,128,128]
    const float* sw = (const float*)d_in[1];   // [32,120,120,81]
    const float* vw = (const float*)d_in[2];   // [16,8,29,29,64]
    const float* dw = (const float*)d_in[3];   // [2,13456]
    const float* db = (const float*)d_in[4];   // [2]
    float* out = (float*)d_out;                // [64,2]

    cudaFuncSetAttribute(v1_kernel, cudaFuncAttributeMaxDynamicSharedMemorySize, V1_SMEM);
    cudaFuncSetAttribute(v4_kernel, cudaFuncAttributeMaxDynamicSharedMemorySize, V4_SMEM);

    v1_kernel<<<NPIX / PPB, 128, V1_SMEM>>>(x, sw);
    v4_kernel<<<V4PIX, 128, V4_SMEM>>>(vw, dw);
    dec2_kernel<<<128, 256>>>(db, out);
}

// round 13
// speedup vs baseline: 1.5395x; 1.5395x over previous
#include <cuda_runtime.h>
#include <cstdint>

#define DIMS   120
#define NPIX   14400        // 120*120
#define SS2    81
#define B64    64
#define PITCH  92           // banks 28g+q all-distinct for scalar fragment loads
#define V4PIX  841          // 29*29
#define FLATN  13456        // 16*841
#define PPB    10           // pixels per v1 block (same image row)

// Intermediates (allocation-free scratch)
__device__ float g_cplx[8 * NPIX * B64];    // [s][pix][b]
__device__ float g_part[V4PIX * 128];       // [p][b*2+cls] decision partials

__device__ __forceinline__ void cp_async4(void* smem_dst, const void* gmem_src) {
    unsigned s = (unsigned)__cvta_generic_to_shared(smem_dst);
    asm volatile("cp.async.ca.shared.global [%0], [%1], 4;" :: "r"(s), "l"(gmem_src));
}
__device__ __forceinline__ void cp_async16(void* smem_dst, const void* gmem_src) {
    unsigned s = (unsigned)__cvta_generic_to_shared(smem_dst);
    asm volatile("cp.async.cg.shared.global [%0], [%1], 16;" :: "r"(s), "l"(gmem_src));
}
__device__ __forceinline__ void cp_commit() {
    asm volatile("cp.async.commit_group;");
}
__device__ __forceinline__ uint32_t to_tf32(float f) {
    uint32_t r;
    asm("cvt.rna.tf32.f32 %0, %1;" : "=r"(r) : "f"(f));
    return r;
}

// ---------------------------------------------------------------------------
// V1 via mma.sync m16n8k8 tf32 — R10 kernel VERBATIM (measured 118.3/118.6us
// in two separate rounds). Scalar LDS.32 fragment loads (bank-perfect at
// pitch 92), weights double-buffered via cp.async, patches staged by
// threads t<81 with constant strides.
// ---------------------------------------------------------------------------
__global__ __launch_bounds__(128)
void v1_kernel(const float* __restrict__ x, const float* __restrict__ w)
{
    extern __shared__ __align__(16) float sm[];
    float (*w_s)[32][PITCH] = (float (*)[32][PITCH])sm;                // [2][32][92]
    float (*p_s)[PITCH]     = (float (*)[PITCH])(sm + 2 * 32 * PITCH); // [64][92]
    float* bounce           = sm + 2 * 32 * PITCH + 64 * PITCH;       // [8*64]

    int t = threadIdx.x;
    int lane = t & 31, wid = t >> 5;
    int g = lane >> 2;
    int q = lane & 3;

    int row_i = blockIdx.x / 12;
    int j0    = (blockIdx.x % 12) * 10;
    int p0    = row_i * DIMS + j0;

    {
        float* rowp = (t < 64) ? &w_s[t >> 5][t & 31][0] : &p_s[t - 64][0];
#pragma unroll
        for (int c = 81; c < 92; c++) rowp[c] = 0.f;
    }

    int r0 = t / 9;
    int q0 = t - 9 * r0;

    auto wpre = [&](int p, int buf) {
#pragma unroll
        for (int gg = 0; gg < 8; gg++) {
            int c = wid * 8 + gg;
            const float* src = w + (c * NPIX + p) * SS2 + lane;
            float* dst = &w_s[buf][c][lane];
            cp_async4(dst, src);
            cp_async4(dst + 32, src + 32);
            if (lane < 17) cp_async4(dst + 64, src + 64);
        }
    };
    auto ppre = [&](int j) {
        if (t < SS2) {
            const float* src = x + (row_i << 7) + j + (r0 << 7) + q0;
            float* dst = &p_s[0][t];
#pragma unroll
            for (int b = 0; b < 64; b++)
                cp_async4(dst + b * PITCH, src + (b << 14));
        }
    };

    wpre(p0, 0);
    cp_commit();
    ppre(j0);
    cp_commit();

    for (int n = 0; n < PPB; n++) {
        int p   = p0 + n;
        int buf = n & 1;

        if (n + 1 < PPB) {
            wpre(p + 1, buf ^ 1);
            cp_commit();
            asm volatile("cp.async.wait_group 1;");
        } else {
            asm volatile("cp.async.wait_group 0;");
        }
        __syncthreads();

        float d[4][4];
#pragma unroll
        for (int nt = 0; nt < 4; nt++)
#pragma unroll
            for (int r = 0; r < 4; r++) d[nt][r] = 0.f;

        const float (*wb)[PITCH] = w_s[buf];
        const float (*pb)[PITCH] = p_s;

#pragma unroll
        for (int kt = 0; kt < 11; kt++) {
            int k0 = kt * 8;
            uint32_t a0 = to_tf32(pb[16 * wid + g][k0 + q]);
            uint32_t a1 = to_tf32(pb[16 * wid + g + 8][k0 + q]);
            uint32_t a2 = to_tf32(pb[16 * wid + g][k0 + q + 4]);
            uint32_t a3 = to_tf32(pb[16 * wid + g + 8][k0 + q + 4]);
#pragma unroll
            for (int nt = 0; nt < 4; nt++) {
                uint32_t b0 = to_tf32(wb[8 * nt + g][k0 + q]);
                uint32_t b1 = to_tf32(wb[8 * nt + g][k0 + q + 4]);
                asm volatile(
                    "mma.sync.aligned.m16n8k8.row.col.f32.tf32.tf32.f32 "
                    "{%0,%1,%2,%3}, {%4,%5,%6,%7}, {%8,%9}, {%0,%1,%2,%3};"
                    : "+f"(d[nt][0]), "+f"(d[nt][1]), "+f"(d[nt][2]), "+f"(d[nt][3])
                    : "r"(a0), "r"(a1), "r"(a2), "r"(a3), "r"(b0), "r"(b1));
            }
        }
        __syncthreads();

        if (n + 1 < PPB) {
            ppre(j0 + n + 1);
            cp_commit();
        }

#pragma unroll
        for (int nt = 0; nt < 4; nt++) {
            float r01 = fmaxf(d[nt][0], 0.f) + fmaxf(d[nt][1], 0.f);
            float r23 = fmaxf(d[nt][2], 0.f) + fmaxf(d[nt][3], 0.f);
            r01 += __shfl_xor_sync(0xFFFFFFFFu, r01, 1);
            r23 += __shfl_xor_sync(0xFFFFFFFFu, r23, 1);
            if ((lane & 1) == 0) {
                int s = 2 * nt + (q >> 1);
                int b = 16 * wid + g;
                bounce[s * 64 + b]     = r01 * 0.25f;
                bounce[s * 64 + b + 8] = r23 * 0.25f;
            }
        }
        __syncthreads();

        {
            int s2i = t >> 4;
            int m   = t & 15;
            float4 v = *(const float4*)&bounce[s2i * 64 + m * 4];
            *(float4*)&g_cplx[(s2i * NPIX + p) * B64 + m * 4] = v;
        }
        __syncthreads();
    }
}

#define V1_SMEM ((2 * 32 * PITCH + 64 * PITCH + 8 * 64) * 4)

// ---------------------------------------------------------------------------
// V4 via mma.sync m16n8k8 tf32 + fused decision fold (R11/R12 verbatim,
// measured ~25us twice).
// ---------------------------------------------------------------------------
__global__ __launch_bounds__(128)
void v4_kernel(const float* __restrict__ vw, const float* __restrict__ dw)
{
    extern __shared__ __align__(16) float vsm[];
    float* wt   = vsm;            // [2][16][68]
    float* ps   = vsm + 2176;     // [2][64][72]
    float* dwv  = vsm + 11392;    // [2][16]
    float* part = vsm + 11424;    // [128]

    int p  = blockIdx.x;
    int ii = p / 29;
    int jj = p - ii * 29;
    int base_pix = (ii * 4) * DIMS + jj * 4;

    int t = threadIdx.x;
    int lane = t & 31, wid = t >> 5;
    int g = lane >> 2;
    int q = lane & 3;

    if (t < 32)
        dwv[t] = dw[(t >> 4) * FLATN + (t & 15) * V4PIX + p];

    auto stage_w = [&](int s, int buf) {
        if (t < 64) {
            int o = t >> 2, c4 = t & 3;
            const float* src = vw + (((o << 3) + s) * V4PIX + p) * 64 + c4 * 16;
            float* dst = &wt[buf * 1088 + o * 68 + c4 * 16];
#pragma unroll
            for (int j = 0; j < 4; j++)
                cp_async16(dst + j * 4, src + j * 4);
        }
    };
    auto stage_p = [&](int s, int buf) {
#pragma unroll
        for (int f0 = 0; f0 < 8; f0++) {
            int f = t + f0 * 128;
            int pos = f >> 4, bq = f & 15;
            int di = pos >> 3, dj = pos & 7;
            const float* src = g_cplx + (size_t)s * (NPIX * B64)
                             + (base_pix + di * DIMS + dj) * B64 + bq * 4;
            cp_async16(&ps[buf * 4608 + pos * 72 + bq * 4], src);
        }
    };

    float d[2][4];
#pragma unroll
    for (int n = 0; n < 2; n++)
#pragma unroll
        for (int r = 0; r < 4; r++) d[n][r] = 0.f;

    stage_w(0, 0);
    stage_p(0, 0);
    cp_commit();

    for (int s = 0; s < 8; s++) {
        int buf = s & 1;
        if (s < 7) {
            stage_w(s + 1, buf ^ 1);
            stage_p(s + 1, buf ^ 1);
            cp_commit();
            asm volatile("cp.async.wait_group 1;");
        } else {
            asm volatile("cp.async.wait_group 0;");
        }
        __syncthreads();

        const float* wb = &wt[buf * 1088];
        const float* pb = &ps[buf * 4608];

#pragma unroll
        for (int kt = 0; kt < 8; kt++) {
            int k0 = kt * 8;
            uint32_t a0 = to_tf32(wb[g * 68 + k0 + q]);
            uint32_t a1 = to_tf32(wb[(g + 8) * 68 + k0 + q]);
            uint32_t a2 = to_tf32(wb[g * 68 + k0 + q + 4]);
            uint32_t a3 = to_tf32(wb[(g + 8) * 68 + k0 + q + 4]);
#pragma unroll
            for (int nl = 0; nl < 2; nl++) {
                int nt = 2 * wid + nl;
                uint32_t b0 = to_tf32(pb[(k0 + q) * 72 + 8 * nt + g]);
                uint32_t b1 = to_tf32(pb[(k0 + q + 4) * 72 + 8 * nt + g]);
                asm volatile(
                    "mma.sync.aligned.m16n8k8.row.col.f32.tf32.tf32.f32 "
                    "{%0,%1,%2,%3}, {%4,%5,%6,%7}, {%8,%9}, {%0,%1,%2,%3};"
                    : "+f"(d[nl][0]), "+f"(d[nl][1]), "+f"(d[nl][2]), "+f"(d[nl][3])
                    : "r"(a0), "r"(a1), "r"(a2), "r"(a3), "r"(b0), "r"(b1));
            }
        }
        __syncthreads();
    }

    float dw0g = dwv[g],      dw0h = dwv[g + 8];
    float dw1g = dwv[16 + g], dw1h = dwv[16 + g + 8];
#pragma unroll
    for (int nl = 0; nl < 2; nl++) {
        int nt = 2 * wid + nl;
        float c00 = d[nl][0] * dw0g + d[nl][2] * dw0h;
        float c01 = d[nl][1] * dw0g + d[nl][3] * dw0h;
        float c10 = d[nl][0] * dw1g + d[nl][2] * dw1h;
        float c11 = d[nl][1] * dw1g + d[nl][3] * dw1h;
#pragma unroll
        for (int m = 4; m < 32; m <<= 1) {
            c00 += __shfl_xor_sync(0xFFFFFFFFu, c00, m);
            c01 += __shfl_xor_sync(0xFFFFFFFFu, c01, m);
            c10 += __shfl_xor_sync(0xFFFFFFFFu, c10, m);
            c11 += __shfl_xor_sync(0xFFFFFFFFu, c11, m);
        }
        if (g == 0) {
            int b = 8 * nt + 2 * q;
            part[b * 2 + 0]       = c00;
            part[(b + 1) * 2 + 0] = c01;
            part[b * 2 + 1]       = c10;
            part[(b + 1) * 2 + 1] = c11;
        }
    }
    __syncthreads();
    g_part[p * 128 + t] = part[t];
}
#define V4_SMEM (11552 * 4)

// ---------------------------------------------------------------------------
// dec2: parallel deterministic reduction (R11/R12 verbatim).
// ---------------------------------------------------------------------------
__global__ __launch_bounds__(256)
void dec2_kernel(const float* __restrict__ db, float* __restrict__ out)
{
    int t = blockIdx.x;          // output index b*2+cls
    int j = threadIdx.x;

    float ssum = 0.f;
    for (int p = j; p < V4PIX; p += 256)
        ssum += g_part[p * 128 + t];

    __shared__ float red[256];
    red[j] = ssum;
    __syncthreads();
    for (int off = 128; off > 0; off >>= 1) {
        if (j < off) red[j] += red[j + off];
        __syncthreads();
    }
    if (j == 0) out[t] = red[0] + db[t & 1];
}

// ---------------------------------------------------------------------------
extern "C" void kernel_launch(void* const* d_in, const int* in_sizes, int n_in,
                              void* d_out, int out_size)
{
    const float* x  = (const float*)d_in[0];   // [64,1,128,128]
    const float* sw = (const float*)d_in[1];   // [32,120,120,81]
    const float* vw = (const float*)d_in[2];   // [16,8,29,29,64]
    const float* dw = (const float*)d_in[3];   // [2,13456]
    const float* db = (const float*)d_in[4];   // [2]
    float* out = (float*)d_out;                // [64,2]

    cudaFuncSetAttribute(v1_kernel, cudaFuncAttributeMaxDynamicSharedMemorySize, V1_SMEM);
    cudaFuncSetAttribute(v4_kernel, cudaFuncAttributeMaxDynamicSharedMemorySize, V4_SMEM);

    v1_kernel<<<NPIX / PPB, 128, V1_SMEM>>>(x, sw);
    v4_kernel<<<V4PIX, 128, V4_SMEM>>>(vw, dw);
    dec2_kernel<<<128, 256>>>(db, out);
}

// round 14
// speedup vs baseline: 1.7495x; 1.1364x over previous
#include <cuda_runtime.h>
#include <cstdint>

#define DIMS   120
#define NPIX   14400        // 120*120
#define SS2    81
#define B64    64
#define PITCH  92           // weights: banks 28g+q all-distinct
#define XBP    210          // x-tile batch pitch (10 rows x 21); bank 18g distinct
#define XRP    21           // x-tile row pitch
#define V4PIX  841          // 29*29
#define FLATN  13456        // 16*841
#define PPB    10           // pixels per v1 block (same image row)

// Intermediates (allocation-free scratch)
__device__ float g_cplx[8 * NPIX * B64];    // [s][pix][b]
__device__ float g_part[V4PIX * 128];       // [p][b*2+cls] decision partials

__device__ __forceinline__ void cp_async4(void* smem_dst, const void* gmem_src) {
    unsigned s = (unsigned)__cvta_generic_to_shared(smem_dst);
    asm volatile("cp.async.ca.shared.global [%0], [%1], 4;" :: "r"(s), "l"(gmem_src));
}
__device__ __forceinline__ void cp_async16(void* smem_dst, const void* gmem_src) {
    unsigned s = (unsigned)__cvta_generic_to_shared(smem_dst);
    asm volatile("cp.async.cg.shared.global [%0], [%1], 16;" :: "r"(s), "l"(gmem_src));
}
__device__ __forceinline__ void cp_commit() {
    asm volatile("cp.async.commit_group;");
}
__device__ __forceinline__ uint32_t to_tf32(float f) {
    uint32_t r;
    asm("cvt.rna.tf32.f32 %0, %1;" : "=r"(r) : "f"(f));
    return r;
}

// ---------------------------------------------------------------------------
// V1 via mma.sync m16n8k8 tf32, 256 threads. The x patch tile for all 10
// pixels is staged ONCE per block ([64 b][10 r][21 c], row 9 = zero pad);
// A-fragments read it directly via precomputed k->(r,c) offsets plus the
// pixel shift. Weights double-buffered via cp.async as before.
// Warp w: m-tile = w>>1 (batches 16mt..16mt+15), n-half = w&1 (n-tiles
// 2nh, 2nh+1).
// ---------------------------------------------------------------------------
__global__ __launch_bounds__(256)
void v1_kernel(const float* __restrict__ x, const float* __restrict__ w)
{
    extern __shared__ __align__(16) float sm[];
    float (*w_s)[32][PITCH] = (float (*)[32][PITCH])sm;         // [2][32][92]
    float* xt               = sm + 2 * 32 * PITCH;              // [64][210]
    float* bounce           = sm + 2 * 32 * PITCH + B64 * XBP;  // [8*64]

    int t = threadIdx.x;
    int lane = t & 31, wid = t >> 5;
    int g = lane >> 2;
    int q = lane & 3;
    int mt = wid >> 1;          // m-tile (batch group)
    int nh = wid & 1;           // n-half

    int row_i = blockIdx.x / 12;
    int j0    = (blockIdx.x % 12) * 10;
    int p0    = row_i * DIMS + j0;

    // zero weight k-padding cols 81..91 (64 rows, threads 0..63)
    if (t < 64) {
        float* rowp = &w_s[t >> 5][t & 31][0];
#pragma unroll
        for (int c = 81; c < 92; c++) rowp[c] = 0.f;
    }
    // zero x-tile pad row r=9 (64 b x 21 cols)
    for (int idx = t; idx < B64 * XRP; idx += 256)
        xt[(idx / XRP) * XBP + 9 * XRP + (idx % XRP)] = 0.f;

    // per-thread A-fragment offsets: offA(k) = (k/9)*21 + k%9
    int offA1[11], offA2[11];
#pragma unroll
    for (int kt = 0; kt < 11; kt++) {
        int k1 = kt * 8 + q;
        int k2 = k1 + 4;
        offA1[kt] = (k1 / 9) * XRP + (k1 % 9);
        offA2[kt] = (k2 / 9) * XRP + (k2 % 9);
    }

    // weight staging: pixel p -> w_s[buf][c][k]; 8 warps x 4 channels
    auto wpre = [&](int p, int buf) {
#pragma unroll
        for (int gg = 0; gg < 4; gg++) {
            int c = wid * 4 + gg;
            const float* src = w + (c * NPIX + p) * SS2 + lane;
            float* dst = &w_s[buf][c][lane];
            cp_async4(dst, src);
            cp_async4(dst + 32, src + 32);
            if (lane < 17) cp_async4(dst + 64, src + 64);
        }
    };

    // --- stage x tile ONCE: xt[b][r][c] = x[b][row_i+r][j0+c], r<9, c<18 ---
    for (int idx = t; idx < B64 * 9 * 18; idx += 256) {
        int b   = idx / 162;
        int rem = idx - b * 162;
        int r   = rem / 18;
        int c   = rem - r * 18;
        cp_async4(&xt[b * XBP + r * XRP + c],
                  x + b * 16384 + (row_i + r) * 128 + j0 + c);
    }
    cp_commit();           // G: xtile
    wpre(p0, 0);
    cp_commit();           // G: W(0)

    for (int n = 0; n < PPB; n++) {
        int p   = p0 + n;
        int buf = n & 1;

        if (n + 1 < PPB) {
            wpre(p + 1, buf ^ 1);
            cp_commit();                               // W(n+1)
            asm volatile("cp.async.wait_group 1;");    // xtile/W(n) done
        } else {
            asm volatile("cp.async.wait_group 0;");
        }
        __syncthreads();

        float d[2][4];     // [n-tile local][frag]
#pragma unroll
        for (int nl = 0; nl < 2; nl++)
#pragma unroll
            for (int r = 0; r < 4; r++) d[nl][r] = 0.f;

        const float (*wb)[PITCH] = w_s[buf];
        const float* pbase = xt + (16 * mt + g) * XBP + n;

#pragma unroll
        for (int kt = 0; kt < 11; kt++) {
            int k0 = kt * 8;
            uint32_t a0 = to_tf32(pbase[offA1[kt]]);
            uint32_t a1 = to_tf32(pbase[8 * XBP + offA1[kt]]);
            uint32_t a2 = to_tf32(pbase[offA2[kt]]);
            uint32_t a3 = to_tf32(pbase[8 * XBP + offA2[kt]]);
#pragma unroll
            for (int nl = 0; nl < 2; nl++) {
                int nt = 2 * nh + nl;
                uint32_t b0 = to_tf32(wb[8 * nt + g][k0 + q]);
                uint32_t b1 = to_tf32(wb[8 * nt + g][k0 + q + 4]);
                asm volatile(
                    "mma.sync.aligned.m16n8k8.row.col.f32.tf32.tf32.f32 "
                    "{%0,%1,%2,%3}, {%4,%5,%6,%7}, {%8,%9}, {%0,%1,%2,%3};"
                    : "+f"(d[nl][0]), "+f"(d[nl][1]), "+f"(d[nl][2]), "+f"(d[nl][3])
                    : "r"(a0), "r"(a1), "r"(a2), "r"(a3), "r"(b0), "r"(b1));
            }
        }
        __syncthreads();   // all reads of w_s[buf] complete

        // relu + phase-mean: s = 2*nt + (q>>1) = 4nh + 2nl + (q>>1)
#pragma unroll
        for (int nl = 0; nl < 2; nl++) {
            float r01 = fmaxf(d[nl][0], 0.f) + fmaxf(d[nl][1], 0.f);
            float r23 = fmaxf(d[nl][2], 0.f) + fmaxf(d[nl][3], 0.f);
            r01 += __shfl_xor_sync(0xFFFFFFFFu, r01, 1);
            r23 += __shfl_xor_sync(0xFFFFFFFFu, r23, 1);
            if ((lane & 1) == 0) {
                int s = 4 * nh + 2 * nl + (q >> 1);
                int b = 16 * mt + g;
                bounce[s * 64 + b]     = r01 * 0.25f;
                bounce[s * 64 + b + 8] = r23 * 0.25f;
            }
        }
        __syncthreads();

        // coalesced store: 8 orient x 64 batch (first 128 threads)
        if (t < 128) {
            int s2i = t >> 4;
            int m   = t & 15;
            float4 v = *(const float4*)&bounce[s2i * 64 + m * 4];
            *(float4*)&g_cplx[(s2i * NPIX + p) * B64 + m * 4] = v;
        }
        __syncthreads();
    }
}

#define V1_SMEM ((2 * 32 * PITCH + B64 * XBP + 8 * 64) * 4)

// ---------------------------------------------------------------------------
// V4 via mma.sync m16n8k8 tf32 + fused decision fold (R11-R13 verbatim).
// ---------------------------------------------------------------------------
__global__ __launch_bounds__(128)
void v4_kernel(const float* __restrict__ vw, const float* __restrict__ dw)
{
    extern __shared__ __align__(16) float vsm[];
    float* wt   = vsm;            // [2][16][68]
    float* ps   = vsm + 2176;     // [2][64][72]
    float* dwv  = vsm + 11392;    // [2][16]
    float* part = vsm + 11424;    // [128]

    int p  = blockIdx.x;
    int ii = p / 29;
    int jj = p - ii * 29;
    int base_pix = (ii * 4) * DIMS + jj * 4;

    int t = threadIdx.x;
    int lane = t & 31, wid = t >> 5;
    int g = lane >> 2;
    int q = lane & 3;

    if (t < 32)
        dwv[t] = dw[(t >> 4) * FLATN + (t & 15) * V4PIX + p];

    auto stage_w = [&](int s, int buf) {
        if (t < 64) {
            int o = t >> 2, c4 = t & 3;
            const float* src = vw + (((o << 3) + s) * V4PIX + p) * 64 + c4 * 16;
            float* dst = &wt[buf * 1088 + o * 68 + c4 * 16];
#pragma unroll
            for (int j = 0; j < 4; j++)
                cp_async16(dst + j * 4, src + j * 4);
        }
    };
    auto stage_p = [&](int s, int buf) {
#pragma unroll
        for (int f0 = 0; f0 < 8; f0++) {
            int f = t + f0 * 128;
            int pos = f >> 4, bq = f & 15;
            int di = pos >> 3, dj = pos & 7;
            const float* src = g_cplx + (size_t)s * (NPIX * B64)
                             + (base_pix + di * DIMS + dj) * B64 + bq * 4;
            cp_async16(&ps[buf * 4608 + pos * 72 + bq * 4], src);
        }
    };

    float d[2][4];
#pragma unroll
    for (int n = 0; n < 2; n++)
#pragma unroll
        for (int r = 0; r < 4; r++) d[n][r] = 0.f;

    stage_w(0, 0);
    stage_p(0, 0);
    cp_commit();

    for (int s = 0; s < 8; s++) {
        int buf = s & 1;
        if (s < 7) {
            stage_w(s + 1, buf ^ 1);
            stage_p(s + 1, buf ^ 1);
            cp_commit();
            asm volatile("cp.async.wait_group 1;");
        } else {
            asm volatile("cp.async.wait_group 0;");
        }
        __syncthreads();

        const float* wb = &wt[buf * 1088];
        const float* pb = &ps[buf * 4608];

#pragma unroll
        for (int kt = 0; kt < 8; kt++) {
            int k0 = kt * 8;
            uint32_t a0 = to_tf32(wb[g * 68 + k0 + q]);
            uint32_t a1 = to_tf32(wb[(g + 8) * 68 + k0 + q]);
            uint32_t a2 = to_tf32(wb[g * 68 + k0 + q + 4]);
            uint32_t a3 = to_tf32(wb[(g + 8) * 68 + k0 + q + 4]);
#pragma unroll
            for (int nl = 0; nl < 2; nl++) {
                int nt = 2 * wid + nl;
                uint32_t b0 = to_tf32(pb[(k0 + q) * 72 + 8 * nt + g]);
                uint32_t b1 = to_tf32(pb[(k0 + q + 4) * 72 + 8 * nt + g]);
                asm volatile(
                    "mma.sync.aligned.m16n8k8.row.col.f32.tf32.tf32.f32 "
                    "{%0,%1,%2,%3}, {%4,%5,%6,%7}, {%8,%9}, {%0,%1,%2,%3};"
                    : "+f"(d[nl][0]), "+f"(d[nl][1]), "+f"(d[nl][2]), "+f"(d[nl][3])
                    : "r"(a0), "r"(a1), "r"(a2), "r"(a3), "r"(b0), "r"(b1));
            }
        }
        __syncthreads();
    }

    float dw0g = dwv[g],      dw0h = dwv[g + 8];
    float dw1g = dwv[16 + g], dw1h = dwv[16 + g + 8];
#pragma unroll
    for (int nl = 0; nl < 2; nl++) {
        int nt = 2 * wid + nl;
        float c00 = d[nl][0] * dw0g + d[nl][2] * dw0h;
        float c01 = d[nl][1] * dw0g + d[nl][3] * dw0h;
        float c10 = d[nl][0] * dw1g + d[nl][2] * dw1h;
        float c11 = d[nl][1] * dw1g + d[nl][3] * dw1h;
#pragma unroll
        for (int m = 4; m < 32; m <<= 1) {
            c00 += __shfl_xor_sync(0xFFFFFFFFu, c00, m);
            c01 += __shfl_xor_sync(0xFFFFFFFFu, c01, m);
            c10 += __shfl_xor_sync(0xFFFFFFFFu, c10, m);
            c11 += __shfl_xor_sync(0xFFFFFFFFu, c11, m);
        }
        if (g == 0) {
            int b = 8 * nt + 2 * q;
            part[b * 2 + 0]       = c00;
            part[(b + 1) * 2 + 0] = c01;
            part[b * 2 + 1]       = c10;
            part[(b + 1) * 2 + 1] = c11;
        }
    }
    __syncthreads();
    g_part[p * 128 + t] = part[t];
}
#define V4_SMEM (11552 * 4)

// ---------------------------------------------------------------------------
// dec2: parallel deterministic reduction (R11-R13 verbatim).
// ---------------------------------------------------------------------------
__global__ __launch_bounds__(256)
void dec2_kernel(const float* __restrict__ db, float* __restrict__ out)
{
    int t = blockIdx.x;          // output index b*2+cls
    int j = threadIdx.x;

    float ssum = 0.f;
    for (int p = j; p < V4PIX; p += 256)
        ssum += g_part[p * 128 + t];

    __shared__ float red[256];
    red[j] = ssum;
    __syncthreads();
    for (int off = 128; off > 0; off >>= 1) {
        if (j < off) red[j] += red[j + off];
        __syncthreads();
    }
    if (j == 0) out[t] = red[0] + db[t & 1];
}

// ---------------------------------------------------------------------------
extern "C" void kernel_launch(void* const* d_in, const int* in_sizes, int n_in,
                              void* d_out, int out_size)
{
    const float* x  = (const float*)d_in[0];   // [64,1,128,128]
    const float* sw = (const float*)d_in[1];   // [32,120,120,81]
    const float* vw = (const float*)d_in[2];   // [16,8,29,29,64]
    const float* dw = (const float*)d_in[3];   // [2,13456]
    const float* db = (const float*)d_in[4];   // [2]
    float* out = (float*)d_out;                // [64,2]

    cudaFuncSetAttribute(v1_kernel, cudaFuncAttributeMaxDynamicSharedMemorySize, V1_SMEM);
    cudaFuncSetAttribute(v4_kernel, cudaFuncAttributeMaxDynamicSharedMemorySize, V4_SMEM);

    v1_kernel<<<NPIX / PPB, 256, V1_SMEM>>>(x, sw);
    v4_kernel<<<V4PIX, 128, V4_SMEM>>>(vw, dw);
    dec2_kernel<<<128, 256>>>(db, out);
}